// round 5
// baseline (speedup 1.0000x reference)
#include <cuda_runtime.h>
#include <cuda_bf16.h>
#include <cstddef>

// Problem constants: N=50000, DEG=32, E=N*32, F=64, K=3, DIM=2, L=3
#define MAXN 50000
#define FDIM 64
#define KF   192        // K * F
#define TILE 64         // nodes per tile

// smem layout (floats):
//   Ws  [192][64]  weights (row-major p, p = k*64+j)        12288 floats
//   gsT0[192][64]  transposed g tile, buffer 0              12288
//   gsT1[192][64]  transposed g tile, buffer 1              12288
//   wf4 [8][32] float4  per-producer-warp edge staging       1024
#define WS_OFF   0
#define G0_OFF   12288
#define G1_OFF   24576
#define WF_OFF   36864
#define SMEM_FLOATS (WF_OFF + 1024)
#define SMEM_BYTES  (SMEM_FLOATS * 4)      // 151552 B -> 1 CTA/SM

__device__ float h_bufA[(size_t)MAXN * FDIM];
__device__ float h_bufB[(size_t)MAXN * FDIM];

// Packed fp32x2 FMA (sm_103a FFMA2 — only reachable via PTX)
#define FMA_F32X2(d, a, b, c) \
    asm("fma.rn.f32x2 %0, %1, %2, %3;" : "=l"(d) : "l"(a), "l"(b), "l"(c))
#define PACK_DUP(d, x) \
    asm("mov.b64 %0, {%1, %1};" : "=l"(d) : "f"(x))
#define UNPACK2(lo, hi, v) \
    asm("mov.b64 {%0, %1}, %2;" : "=f"(lo), "=f"(hi) : "l"(v))

// ---------------------------------------------------------------------------
// Warp-specialized fused layer kernel.
//   Producers (warps 0-7): per stage, aggregate 64-node tile into gsT[s&1],
//     written transposed (gsT[p][swz-pos(r)]) so consumers read row-pairs.
//   Consumers (warps 8-15): per stage, GEMM gsT[(s-1)&1] -> out rows.
// ---------------------------------------------------------------------------
__global__ __launch_bounds__(512, 1)
void fused_layer(const float* __restrict__ h,
                 const float* __restrict__ pseudo,   // [E,2]
                 const int*   __restrict__ rowptr,   // [N+1]
                 const int*   __restrict__ colind,   // [E]
                 const float* __restrict__ pW,       // [2,2]
                 const float* __restrict__ pb,       // [2]
                 const float* __restrict__ mu,       // [K,2]
                 const float* __restrict__ isg,      // [K,2]
                 const float* __restrict__ W,        // fc_W layer: [64,192]
                 float* __restrict__ out, int n)
{
    extern __shared__ float smem[];
    float* Ws   = smem + WS_OFF;    // [192][64] Ws[p*64+f]
    float* gbuf[2] = { smem + G0_OFF, smem + G1_OFF };
    float4* wf4 = (float4*)(smem + WF_OFF);   // [8][32]

    const int tid = threadIdx.x;
    const int wid = tid >> 5;
    const int lid = tid & 31;
    const bool producer = (wid < 8);

    // Load weights once: Ws[p][f], p = k*64+j -> W[j*192 + k*64 + f]
    for (int idx = tid; idx < 192 * 64; idx += 512) {
        const int p = idx >> 6, f = idx & 63;
        const int j = p & 63, k = p >> 6;
        Ws[idx] = __ldg(&W[j * 192 + k * 64 + f]);
    }

    // Producer scalar params
    const float W00 = pW[0], W01 = pW[1], W10 = pW[2], W11 = pW[3];
    const float b0 = pb[0], b1 = pb[1];
    const float m00 = mu[0], m01 = mu[1], m10 = mu[2], m11 = mu[3], m20 = mu[4], m21 = mu[5];
    const float s00 = isg[0]*isg[0], s01 = isg[1]*isg[1];
    const float s10 = isg[2]*isg[2], s11 = isg[3]*isg[3];
    const float s20 = isg[4]*isg[4], s21 = isg[5]*isg[5];
    const float2* __restrict__ ps2 = (const float2*)pseudo;

    // Consumer thread mapping (warps 8-15): ct in 0..255
    const int ct = tid - 256;
    const int tx = ct & 15;        // col group: cols 4tx..+3
    const int ty = ct >> 4;        // row group: rows 4ty..+3 (0..15)

    const int ntiles = (n + TILE - 1) / TILE;
    // number of stages (tiles) this block owns
    int nst = 0;
    if (blockIdx.x < ntiles) nst = (ntiles - blockIdx.x + gridDim.x - 1) / gridDim.x;

    for (int s = 0; s <= nst; s++) {
        // ---------------- Producers: fill gsT[s&1] with tile t_s -----------
        if (s < nst && producer) {
            float* gsT = gbuf[s & 1];
            const int tile = blockIdx.x + s * gridDim.x;
            const int r0 = tile * TILE;
            float4* wfw = wf4 + (wid << 5);

            for (int j = 0; j < 8; j++) {
                const int r = (wid << 3) + j;
                const int node = r0 + r;
                if (node >= n) break;

                const int e0 = rowptr[node], e1 = rowptr[node + 1];
                unsigned long long A0 = 0ULL, A1 = 0ULL, A2 = 0ULL;

                for (int base = e0; base < e1; base += 32) {
                    const int cnt = min(32, e1 - base);
                    if (lid < cnt) {
                        const int e = base + lid;
                        float2 ps = __ldg(&ps2[e]);
                        float u0 = tanhf(fmaf(ps.y, W10, fmaf(ps.x, W00, b0)));
                        float u1 = tanhf(fmaf(ps.y, W11, fmaf(ps.x, W01, b1)));
                        float d0 = u0 - m00, d1 = u1 - m01;
                        float w0 = __expf(-0.5f * (d0*d0*s00 + d1*d1*s01));
                        d0 = u0 - m10; d1 = u1 - m11;
                        float w1 = __expf(-0.5f * (d0*d0*s10 + d1*d1*s11));
                        d0 = u0 - m20; d1 = u1 - m21;
                        float w2 = __expf(-0.5f * (d0*d0*s20 + d1*d1*s21));
                        wfw[lid] = make_float4(w0, w1, w2,
                                               __int_as_float(__ldg(&colind[e])));
                    }
                    __syncwarp();
                    #pragma unroll 8
                    for (int t = 0; t < cnt; t++) {
                        const float4 wt = wfw[t];
                        const int src = __float_as_int(wt.w);
                        const unsigned long long hv =
                            *(const unsigned long long*)(h + (size_t)src * FDIM + 2 * lid);
                        unsigned long long w0d, w1d, w2d;
                        PACK_DUP(w0d, wt.x); PACK_DUP(w1d, wt.y); PACK_DUP(w2d, wt.z);
                        FMA_F32X2(A0, hv, w0d, A0);
                        FMA_F32X2(A1, hv, w1d, A1);
                        FMA_F32X2(A2, hv, w2d, A2);
                    }
                    __syncwarp();
                }

                // transposed + swizzled store: pos = r ^ ((lid>>1 & 7) << 2)
                const int pos = r ^ (((lid >> 1) & 7) << 2);
                float lo, hi;
                UNPACK2(lo, hi, A0);
                gsT[(2 * lid    ) * 64 + pos] = lo;
                gsT[(2 * lid + 1) * 64 + pos] = hi;
                UNPACK2(lo, hi, A1);
                gsT[(64 + 2 * lid    ) * 64 + pos] = lo;
                gsT[(64 + 2 * lid + 1) * 64 + pos] = hi;
                UNPACK2(lo, hi, A2);
                gsT[(128 + 2 * lid    ) * 64 + pos] = lo;
                gsT[(128 + 2 * lid + 1) * 64 + pos] = hi;
            }
        }

        // ---------------- Consumers: GEMM gsT[(s-1)&1], tile t_{s-1} -------
        if (s > 0 && !producer) {
            const float* gsT = gbuf[(s - 1) & 1];
            const int tile = blockIdx.x + (s - 1) * gridDim.x;
            const int r0 = tile * TILE;
            const int rows = min(TILE, n - r0);

            // acc[i][c]: packed rows (4ty+2i, 4ty+2i+1), col 4tx+c
            unsigned long long acc[2][4];
            #pragma unroll
            for (int i = 0; i < 2; i++)
                #pragma unroll
                for (int c = 0; c < 4; c++) acc[i][c] = 0ULL;

            const int ty4 = ty << 2;
            #pragma unroll 4
            for (int p = 0; p < 192; p++) {
                const int b0r = ty4 ^ (((p >> 2) & 7) << 2);
                const ulonglong2 ga = *(const ulonglong2*)(gsT + p * 64 + b0r);
                const float4 wv = *(const float4*)(Ws + p * 64 + (tx << 2));
                unsigned long long w0, w1, w2, w3;
                PACK_DUP(w0, wv.x); PACK_DUP(w1, wv.y);
                PACK_DUP(w2, wv.z); PACK_DUP(w3, wv.w);
                FMA_F32X2(acc[0][0], ga.x, w0, acc[0][0]);
                FMA_F32X2(acc[0][1], ga.x, w1, acc[0][1]);
                FMA_F32X2(acc[0][2], ga.x, w2, acc[0][2]);
                FMA_F32X2(acc[0][3], ga.x, w3, acc[0][3]);
                FMA_F32X2(acc[1][0], ga.y, w0, acc[1][0]);
                FMA_F32X2(acc[1][1], ga.y, w1, acc[1][1]);
                FMA_F32X2(acc[1][2], ga.y, w2, acc[1][2]);
                FMA_F32X2(acc[1][3], ga.y, w3, acc[1][3]);
            }

            #pragma unroll
            for (int i = 0; i < 2; i++) {
                float lx, hx, ly, hy, lz, hz, lw, hw;
                UNPACK2(lx, hx, acc[i][0]);
                UNPACK2(ly, hy, acc[i][1]);
                UNPACK2(lz, hz, acc[i][2]);
                UNPACK2(lw, hw, acc[i][3]);
                const int rA = ty4 + 2 * i;
                if (rA < rows)
                    *(float4*)&out[(size_t)(r0 + rA) * FDIM + (tx << 2)] =
                        make_float4(lx, ly, lz, lw);
                if (rA + 1 < rows)
                    *(float4*)&out[(size_t)(r0 + rA + 1) * FDIM + (tx << 2)] =
                        make_float4(hx, hy, hz, hw);
            }
        }

        __syncthreads();
    }
}

// ---------------------------------------------------------------------------
extern "C" void kernel_launch(void* const* d_in, const int* in_sizes, int n_in,
                              void* d_out, int out_size)
{
    const float* feat   = (const float*)d_in[0];
    const float* pseudo = (const float*)d_in[1];
    const int*   rowptr = (const int*)  d_in[2];
    const int*   colind = (const int*)  d_in[3];
    const float* projW  = (const float*)d_in[4];  // [L,2,2]
    const float* projb  = (const float*)d_in[5];  // [L,2]
    const float* fcW    = (const float*)d_in[6];  // [L,64,192]
    const float* mu     = (const float*)d_in[7];  // [L,3,2]
    const float* isg    = (const float*)d_in[8];  // [L,3,2]

    const int n  = in_sizes[0] / FDIM;
    const int nL = in_sizes[6] / (FDIM * KF);

    void *hap, *hbp;
    cudaGetSymbolAddress(&hap, h_bufA);
    cudaGetSymbolAddress(&hbp, h_bufB);
    float* hbufs[2] = { (float*)hap, (float*)hbp };

    cudaFuncSetAttribute(fused_layer, cudaFuncAttributeMaxDynamicSharedMemorySize, SMEM_BYTES);

    const int ntiles = (n + TILE - 1) / TILE;
    const int grid = ntiles < 148 ? ntiles : 148;   // persistent, 1 CTA/SM

    const float* hin = feat;
    for (int i = 0; i < nL; i++) {
        float* hout = (i == nL - 1) ? (float*)d_out : hbufs[i & 1];
        fused_layer<<<grid, 512, SMEM_BYTES>>>(hin, pseudo, rowptr, colind,
                                               projW + i * 4, projb + i * 2,
                                               mu + i * 6, isg + i * 6,
                                               fcW + i * (FDIM * KF), hout, n);
        hin = hout;
    }
}